// round 3
// baseline (speedup 1.0000x reference)
#include <cuda_runtime.h>
#include <math.h>

#define FDIM 256
#define H 128
#define NMAX 50000

// Single scratch arena (allocation-free rule: __device__ global).
// Layout: buf0 | buf1 | buf2 | dis
#define BUF0_OFF 0
#define BUF1_OFF (NMAX * H)
#define BUF2_OFF (2 * NMAX * H)
#define DIS_OFF  (3 * NMAX * H)
__device__ float g_scratch[3 * NMAX * H + NMAX];

// Resolve: external pointer if non-null, else scratch arena + offset.
__device__ __forceinline__ const float* rsv(const float* p, int off) {
    return p ? p : (g_scratch + off);
}

// ---------------------------------------------------------------------------
// small utility kernels (operate on dis region of scratch)
// ---------------------------------------------------------------------------
__global__ void init_ones_kernel(int n) {
    int i = blockIdx.x * blockDim.x + threadIdx.x;
    if (i < n) g_scratch[DIS_OFF + i] = 1.0f;  // self-loop contributes 1
}

__global__ void deg_acc_kernel(const int* __restrict__ ei, int E) {
    int e = blockIdx.x * blockDim.x + threadIdx.x;
    if (e < E) {
        int d = ei[(size_t)E + e];  // dst row of edge_index (int32)
        atomicAdd(&g_scratch[DIS_OFF + d], 1.0f);
    }
}

__global__ void rsqrt_kernel(int n) {
    int i = blockIdx.x * blockDim.x + threadIdx.x;
    if (i < n) g_scratch[DIS_OFF + i] = rsqrtf(g_scratch[DIS_OFF + i]);
}

// ---------------------------------------------------------------------------
// SGEMM, N fixed to 128. C[M,128] = op_in(A[M,K]) @ W[K,128] (+bias) (relu?)
// 128x128 block tile, BK=8, 256 threads, 8x8 per-thread tile.
// A: external if Aext!=nullptr else scratch+aOff.  C: always scratch+cOff.
// ---------------------------------------------------------------------------
template <bool RIN, bool ROUT, bool BIAS>
__global__ __launch_bounds__(256)
void sgemm_n128(const float* __restrict__ Aext, int aOff,
                const float* __restrict__ W,
                const float* __restrict__ bias,
                int cOff, int M, int K) {
    const float* A = rsv(Aext, aOff);
    float* C = g_scratch + cOff;

    __shared__ float As[8][128];
    __shared__ float Bs[8][128];

    const int tid = threadIdx.x;
    const int rowBase = blockIdx.x * 128;

    const int innerRowA = tid >> 1;          // 0..127
    const int innerColA = (tid & 1) * 4;     // 0 or 4
    const int innerRowB = tid >> 5;          // 0..7
    const int innerColB = (tid & 31) * 4;    // 0..124

    const int tr = tid >> 4;                 // 0..15
    const int tc = tid & 15;                 // 0..15

    float acc[8][8];
#pragma unroll
    for (int i = 0; i < 8; i++)
#pragma unroll
        for (int j = 0; j < 8; j++) acc[i][j] = 0.0f;

    const int mA = rowBase + innerRowA;
    const bool validA = (mA < M);
    const float* Aptr = A + (size_t)mA * K;

    for (int k0 = 0; k0 < K; k0 += 8) {
        float4 av = make_float4(0.f, 0.f, 0.f, 0.f);
        if (validA) av = *(const float4*)(Aptr + k0 + innerColA);
        if (RIN) {
            av.x = fmaxf(av.x, 0.f); av.y = fmaxf(av.y, 0.f);
            av.z = fmaxf(av.z, 0.f); av.w = fmaxf(av.w, 0.f);
        }
        As[innerColA + 0][innerRowA] = av.x;
        As[innerColA + 1][innerRowA] = av.y;
        As[innerColA + 2][innerRowA] = av.z;
        As[innerColA + 3][innerRowA] = av.w;

        float4 bv = *(const float4*)(W + (size_t)(k0 + innerRowB) * 128 + innerColB);
        *(float4*)&Bs[innerRowB][innerColB] = bv;

        __syncthreads();

#pragma unroll
        for (int k = 0; k < 8; k++) {
            float rm[8], rn[8];
#pragma unroll
            for (int i = 0; i < 8; i++) rm[i] = As[k][tr * 8 + i];
#pragma unroll
            for (int j = 0; j < 8; j++) rn[j] = Bs[k][tc * 8 + j];
#pragma unroll
            for (int i = 0; i < 8; i++)
#pragma unroll
                for (int j = 0; j < 8; j++) acc[i][j] += rm[i] * rn[j];
        }
        __syncthreads();
    }

#pragma unroll
    for (int i = 0; i < 8; i++) {
        int row = rowBase + tr * 8 + i;
        if (row >= M) continue;
#pragma unroll
        for (int j = 0; j < 8; j += 4) {
            int col = tc * 8 + j;
            float4 v;
            v.x = acc[i][j + 0];
            v.y = acc[i][j + 1];
            v.z = acc[i][j + 2];
            v.w = acc[i][j + 3];
            if (BIAS) {
                v.x += bias[col + 0]; v.y += bias[col + 1];
                v.z += bias[col + 2]; v.w += bias[col + 3];
            }
            if (ROUT) {
                v.x = fmaxf(v.x, 0.f); v.y = fmaxf(v.y, 0.f);
                v.z = fmaxf(v.z, 0.f); v.w = fmaxf(v.w, 0.f);
            }
            *(float4*)(C + (size_t)row * 128 + col) = v;
        }
    }
}

// ---------------------------------------------------------------------------
// GCN aggregation. init: out[i] = bias + dis[i]^2 * xw[i]  (self loop + bias)
// scatter: out[dst] += dis[src]*dis[dst] * xw[src]   (one warp per edge)
// ---------------------------------------------------------------------------
__global__ void gcn_init_kernel(int xwOff, const float* __restrict__ bias,
                                int outOff, int n) {
    const float* xw = g_scratch + xwOff;
    const float* dis = g_scratch + DIS_OFF;
    float* out = g_scratch + outOff;
    int idx = blockIdx.x * blockDim.x + threadIdx.x;  // n * 32 float4 slots
    if (idx >= n * 32) return;
    int i = idx >> 5;
    int f4 = idx & 31;
    float di = dis[i];
    float sn = di * di;
    float4 x = ((const float4*)(xw + (size_t)i * H))[f4];
    float4 b = ((const float4*)bias)[f4];
    float4 o;
    o.x = b.x + sn * x.x; o.y = b.y + sn * x.y;
    o.z = b.z + sn * x.z; o.w = b.w + sn * x.w;
    ((float4*)(out + (size_t)i * H))[f4] = o;
}

__global__ void scatter_kernel(const int* __restrict__ ei,
                               int xwOff, int outOff, int E) {
    const float* xw = g_scratch + xwOff;
    const float* dis = g_scratch + DIS_OFF;
    float* out = g_scratch + outOff;
    int w = (blockIdx.x * blockDim.x + threadIdx.x) >> 5;
    int lane = threadIdx.x & 31;
    if (w >= E) return;
    int s = ei[w];
    int d = ei[(size_t)E + w];
    float nrm = dis[s] * dis[d];
    float4 v = ((const float4*)(xw + (size_t)s * H))[lane];
    float* dst = out + (size_t)d * H + lane * 4;
    atomicAdd(dst + 0, nrm * v.x);
    atomicAdd(dst + 1, nrm * v.y);
    atomicAdd(dst + 2, nrm * v.z);
    atomicAdd(dst + 3, nrm * v.w);
}

// ---------------------------------------------------------------------------
// Edge classifier: out[e] = sigmoid( dot(relu(A[src]+B[dst]), w2) + b2 )
// (cls_b1 folded into A via the GEMM bias epilogue.)  One warp per edge.
// ---------------------------------------------------------------------------
__global__ void edge_cls_kernel(const int* __restrict__ ei,
                                int aOff, int bOff,
                                const float* __restrict__ w2,
                                const float* __restrict__ b2,
                                float* __restrict__ out, int E) {
    const float* Amat = g_scratch + aOff;
    const float* Bmat = g_scratch + bOff;
    int w = (blockIdx.x * blockDim.x + threadIdx.x) >> 5;
    int lane = threadIdx.x & 31;
    if (w >= E) return;
    int s = ei[w];
    int d = ei[(size_t)E + w];
    float4 a = ((const float4*)(Amat + (size_t)s * H))[lane];
    float4 b = ((const float4*)(Bmat + (size_t)d * H))[lane];
    float4 ww = ((const float4*)w2)[lane];
    float p = fmaxf(a.x + b.x, 0.f) * ww.x
            + fmaxf(a.y + b.y, 0.f) * ww.y
            + fmaxf(a.z + b.z, 0.f) * ww.z
            + fmaxf(a.w + b.w, 0.f) * ww.w;
#pragma unroll
    for (int off = 16; off; off >>= 1)
        p += __shfl_xor_sync(0xffffffffu, p, off);
    if (lane == 0) {
        float z = p + b2[0];
        out[w] = 1.0f / (1.0f + __expf(-z));
    }
}

// ---------------------------------------------------------------------------
extern "C" void kernel_launch(void* const* d_in, const int* in_sizes, int n_in,
                              void* d_out, int out_size) {
    const float* nf      = (const float*)d_in[0];
    const int*   ei      = (const int*)d_in[1];   // int32 (JAX x64 disabled)
    const float* enc_w1  = (const float*)d_in[2];
    const float* enc_b1  = (const float*)d_in[3];
    const float* enc_w2  = (const float*)d_in[4];
    const float* enc_b2  = (const float*)d_in[5];
    const float* conv_w1 = (const float*)d_in[6];
    const float* conv_b1 = (const float*)d_in[7];
    const float* conv_w2 = (const float*)d_in[8];
    const float* conv_b2 = (const float*)d_in[9];
    const float* conv_w3 = (const float*)d_in[10];
    const float* conv_b3 = (const float*)d_in[11];
    const float* cls_w1  = (const float*)d_in[12];
    const float* cls_b1  = (const float*)d_in[13];
    const float* cls_w2  = (const float*)d_in[14];
    const float* cls_b2  = (const float*)d_in[15];

    const int n = in_sizes[0] / FDIM;
    const int E = in_sizes[1] / 2;

    const int T = 256;
    const int gm = (n + 127) / 128;
    const int gInit = (n * 32 + T - 1) / T;
    const long long eThreads = (long long)E * 32;
    const int gEdge = (int)((eThreads + T - 1) / T);

    // degrees -> dis
    init_ones_kernel<<<(n + T - 1) / T, T>>>(n);
    deg_acc_kernel<<<(E + T - 1) / T, T>>>(ei, E);
    rsqrt_kernel<<<(n + T - 1) / T, T>>>(n);

    // node encoder: buf1 = relu(nf@W1+b1e)@W2 + b2e
    sgemm_n128<false, true, true><<<gm, 256>>>(nf, 0, enc_w1, enc_b1, BUF0_OFF, n, FDIM);
    sgemm_n128<false, false, true><<<gm, 256>>>(nullptr, BUF0_OFF, enc_w2, enc_b2, BUF1_OFF, n, H);

    // conv1: input buf1 -> raw output buf2 (relu deferred to next GEMM input)
    sgemm_n128<false, false, false><<<gm, 256>>>(nullptr, BUF1_OFF, conv_w1, nullptr, BUF0_OFF, n, H);
    gcn_init_kernel<<<gInit, T>>>(BUF0_OFF, conv_b1, BUF2_OFF, n);
    scatter_kernel<<<gEdge, T>>>(ei, BUF0_OFF, BUF2_OFF, E);

    // conv2: input relu(buf2) -> raw output buf1
    sgemm_n128<true, false, false><<<gm, 256>>>(nullptr, BUF2_OFF, conv_w2, nullptr, BUF0_OFF, n, H);
    gcn_init_kernel<<<gInit, T>>>(BUF0_OFF, conv_b2, BUF1_OFF, n);
    scatter_kernel<<<gEdge, T>>>(ei, BUF0_OFF, BUF1_OFF, E);

    // conv3: input relu(buf1) -> raw output buf2 (no relu)
    sgemm_n128<true, false, false><<<gm, 256>>>(nullptr, BUF1_OFF, conv_w3, nullptr, BUF0_OFF, n, H);
    gcn_init_kernel<<<gInit, T>>>(BUF0_OFF, conv_b3, BUF2_OFF, n);
    scatter_kernel<<<gEdge, T>>>(ei, BUF0_OFF, BUF2_OFF, E);

    // classifier partials: A = X@W1_top + cls_b1 (buf0), B = X@W1_bot (buf1)
    sgemm_n128<false, false, true><<<gm, 256>>>(nullptr, BUF2_OFF, cls_w1, cls_b1, BUF0_OFF, n, H);
    sgemm_n128<false, false, false><<<gm, 256>>>(nullptr, BUF2_OFF, cls_w1 + 128 * 128, nullptr, BUF1_OFF, n, H);

    // per-edge score
    edge_cls_kernel<<<gEdge, T>>>(ei, BUF0_OFF, BUF1_OFF, cls_w2, cls_b2, (float*)d_out, E);
}

// round 4
// speedup vs baseline: 2.1709x; 2.1709x over previous
#include <cuda_runtime.h>
#include <math.h>

#define FDIM 256
#define H 128
#define NMAX 50000
#define EMAX 1600000

// Scratch (allocation-free rule: __device__ globals)
#define BUF0_OFF 0
#define BUF1_OFF (NMAX * H)
#define BUF2_OFF (2 * NMAX * H)
__device__ float g_scratch[3 * NMAX * H];
__device__ float g_dis[NMAX];
__device__ int   g_cnt[NMAX];
__device__ int   g_fill[NMAX];
__device__ int   g_rowptr[NMAX + 1];
__device__ int   g_csr_src[EMAX];
__device__ float g_csr_norm[EMAX];

__device__ __forceinline__ const float* rsv(const float* p, int off) {
    return p ? p : (g_scratch + off);
}

// ---------------------------------------------------------------------------
// CSR build: count -> dis -> scan -> fill
// ---------------------------------------------------------------------------
__global__ void zero_int_kernel(int n) {
    int i = blockIdx.x * blockDim.x + threadIdx.x;
    if (i < n) { g_cnt[i] = 0; g_fill[i] = 0; }
}

__global__ void count_kernel(const int* __restrict__ ei, int E) {
    int e = blockIdx.x * blockDim.x + threadIdx.x;
    if (e < E) atomicAdd(&g_cnt[ei[(size_t)E + e]], 1);
}

__global__ void dis_kernel(int n) {
    int i = blockIdx.x * blockDim.x + threadIdx.x;
    if (i < n) g_dis[i] = rsqrtf((float)(g_cnt[i] + 1));  // +1 self loop
}

// single-block exclusive scan of g_cnt -> g_rowptr (n up to ~50k)
__global__ void scan_kernel(int n, int E) {
    __shared__ int ssum[1024];
    const int t = threadIdx.x;
    const int C = (n + 1023) >> 10;
    const int b = t * C;
    const int e = min(b + C, n);
    int s = 0;
    for (int i = b; i < e; i++) s += g_cnt[i];
    ssum[t] = s;
    __syncthreads();
    // Hillis-Steele inclusive scan over ssum
    for (int off = 1; off < 1024; off <<= 1) {
        int tmp = (t >= off) ? ssum[t - off] : 0;
        __syncthreads();
        ssum[t] += tmp;
        __syncthreads();
    }
    int run = ssum[t] - s;  // exclusive offset for this thread's chunk
    for (int i = b; i < e; i++) { g_rowptr[i] = run; run += g_cnt[i]; }
    if (t == 0) g_rowptr[n] = E;
}

__global__ void fill_kernel(const int* __restrict__ ei, int E) {
    int e = blockIdx.x * blockDim.x + threadIdx.x;
    if (e >= E) return;
    int s = ei[e];
    int d = ei[(size_t)E + e];
    int pos = g_rowptr[d] + atomicAdd(&g_fill[d], 1);
    g_csr_src[pos] = s;
    g_csr_norm[pos] = g_dis[s] * g_dis[d];
}

// ---------------------------------------------------------------------------
// SGEMM, N fixed to 128. C[M,128] = op_in(A[M,K]) @ W[K,128] (+bias) (relu?)
// ---------------------------------------------------------------------------
template <bool RIN, bool ROUT, bool BIAS>
__global__ __launch_bounds__(256)
void sgemm_n128(const float* __restrict__ Aext, int aOff,
                const float* __restrict__ W,
                const float* __restrict__ bias,
                int cOff, int M, int K) {
    const float* A = rsv(Aext, aOff);
    float* C = g_scratch + cOff;

    __shared__ float As[8][128];
    __shared__ float Bs[8][128];

    const int tid = threadIdx.x;
    const int rowBase = blockIdx.x * 128;

    const int innerRowA = tid >> 1;
    const int innerColA = (tid & 1) * 4;
    const int innerRowB = tid >> 5;
    const int innerColB = (tid & 31) * 4;

    const int tr = tid >> 4;
    const int tc = tid & 15;

    float acc[8][8];
#pragma unroll
    for (int i = 0; i < 8; i++)
#pragma unroll
        for (int j = 0; j < 8; j++) acc[i][j] = 0.0f;

    const int mA = rowBase + innerRowA;
    const bool validA = (mA < M);
    const float* Aptr = A + (size_t)mA * K;

    for (int k0 = 0; k0 < K; k0 += 8) {
        float4 av = make_float4(0.f, 0.f, 0.f, 0.f);
        if (validA) av = *(const float4*)(Aptr + k0 + innerColA);
        if (RIN) {
            av.x = fmaxf(av.x, 0.f); av.y = fmaxf(av.y, 0.f);
            av.z = fmaxf(av.z, 0.f); av.w = fmaxf(av.w, 0.f);
        }
        As[innerColA + 0][innerRowA] = av.x;
        As[innerColA + 1][innerRowA] = av.y;
        As[innerColA + 2][innerRowA] = av.z;
        As[innerColA + 3][innerRowA] = av.w;

        float4 bv = *(const float4*)(W + (size_t)(k0 + innerRowB) * 128 + innerColB);
        *(float4*)&Bs[innerRowB][innerColB] = bv;

        __syncthreads();

#pragma unroll
        for (int k = 0; k < 8; k++) {
            float rm[8], rn[8];
#pragma unroll
            for (int i = 0; i < 8; i++) rm[i] = As[k][tr * 8 + i];
#pragma unroll
            for (int j = 0; j < 8; j++) rn[j] = Bs[k][tc * 8 + j];
#pragma unroll
            for (int i = 0; i < 8; i++)
#pragma unroll
                for (int j = 0; j < 8; j++) acc[i][j] += rm[i] * rn[j];
        }
        __syncthreads();
    }

#pragma unroll
    for (int i = 0; i < 8; i++) {
        int row = rowBase + tr * 8 + i;
        if (row >= M) continue;
#pragma unroll
        for (int j = 0; j < 8; j += 4) {
            int col = tc * 8 + j;
            float4 v;
            v.x = acc[i][j + 0];
            v.y = acc[i][j + 1];
            v.z = acc[i][j + 2];
            v.w = acc[i][j + 3];
            if (BIAS) {
                v.x += bias[col + 0]; v.y += bias[col + 1];
                v.z += bias[col + 2]; v.w += bias[col + 3];
            }
            if (ROUT) {
                v.x = fmaxf(v.x, 0.f); v.y = fmaxf(v.y, 0.f);
                v.z = fmaxf(v.z, 0.f); v.w = fmaxf(v.w, 0.f);
            }
            *(float4*)(C + (size_t)row * 128 + col) = v;
        }
    }
}

// ---------------------------------------------------------------------------
// GCN aggregation (gather, no atomics): one warp per dst node.
// out[d] = bias + dis[d]^2 * xw[d] + sum_{e in csr[d]} norm[e] * xw[src[e]]
// ---------------------------------------------------------------------------
__global__ __launch_bounds__(256)
void aggregate_kernel(int xwOff, const float* __restrict__ bias,
                      int outOff, int n) {
    const float4* xw4 = (const float4*)(g_scratch + xwOff);
    float4* out4 = (float4*)(g_scratch + outOff);
    int d = (blockIdx.x * blockDim.x + threadIdx.x) >> 5;
    int lane = threadIdx.x & 31;
    if (d >= n) return;

    float di = g_dis[d];
    float sn = di * di;
    float4 b = ((const float4*)bias)[lane];
    float4 x = xw4[(size_t)d * 32 + lane];
    float4 acc;
    acc.x = b.x + sn * x.x; acc.y = b.y + sn * x.y;
    acc.z = b.z + sn * x.z; acc.w = b.w + sn * x.w;

    int i = g_rowptr[d];
    const int end = g_rowptr[d + 1];
    for (; i + 1 < end; i += 2) {
        int s0 = g_csr_src[i], s1 = g_csr_src[i + 1];
        float n0 = g_csr_norm[i], n1 = g_csr_norm[i + 1];
        float4 v0 = xw4[(size_t)s0 * 32 + lane];
        float4 v1 = xw4[(size_t)s1 * 32 + lane];
        acc.x += n0 * v0.x + n1 * v1.x;
        acc.y += n0 * v0.y + n1 * v1.y;
        acc.z += n0 * v0.z + n1 * v1.z;
        acc.w += n0 * v0.w + n1 * v1.w;
    }
    if (i < end) {
        int s0 = g_csr_src[i];
        float n0 = g_csr_norm[i];
        float4 v0 = xw4[(size_t)s0 * 32 + lane];
        acc.x += n0 * v0.x; acc.y += n0 * v0.y;
        acc.z += n0 * v0.z; acc.w += n0 * v0.w;
    }
    out4[(size_t)d * 32 + lane] = acc;
}

// ---------------------------------------------------------------------------
// Edge classifier: out[e] = sigmoid( dot(relu(A[src]+B[dst]), w2) + b2 )
// ---------------------------------------------------------------------------
__global__ void edge_cls_kernel(const int* __restrict__ ei,
                                int aOff, int bOff,
                                const float* __restrict__ w2,
                                const float* __restrict__ b2,
                                float* __restrict__ out, int E) {
    const float* Amat = g_scratch + aOff;
    const float* Bmat = g_scratch + bOff;
    int w = (blockIdx.x * blockDim.x + threadIdx.x) >> 5;
    int lane = threadIdx.x & 31;
    if (w >= E) return;
    int s = ei[w];
    int d = ei[(size_t)E + w];
    float4 a = ((const float4*)(Amat + (size_t)s * H))[lane];
    float4 b = ((const float4*)(Bmat + (size_t)d * H))[lane];
    float4 ww = ((const float4*)w2)[lane];
    float p = fmaxf(a.x + b.x, 0.f) * ww.x
            + fmaxf(a.y + b.y, 0.f) * ww.y
            + fmaxf(a.z + b.z, 0.f) * ww.z
            + fmaxf(a.w + b.w, 0.f) * ww.w;
#pragma unroll
    for (int off = 16; off; off >>= 1)
        p += __shfl_xor_sync(0xffffffffu, p, off);
    if (lane == 0) {
        float z = p + b2[0];
        out[w] = 1.0f / (1.0f + __expf(-z));
    }
}

// ---------------------------------------------------------------------------
extern "C" void kernel_launch(void* const* d_in, const int* in_sizes, int n_in,
                              void* d_out, int out_size) {
    const float* nf      = (const float*)d_in[0];
    const int*   ei      = (const int*)d_in[1];
    const float* enc_w1  = (const float*)d_in[2];
    const float* enc_b1  = (const float*)d_in[3];
    const float* enc_w2  = (const float*)d_in[4];
    const float* enc_b2  = (const float*)d_in[5];
    const float* conv_w1 = (const float*)d_in[6];
    const float* conv_b1 = (const float*)d_in[7];
    const float* conv_w2 = (const float*)d_in[8];
    const float* conv_b2 = (const float*)d_in[9];
    const float* conv_w3 = (const float*)d_in[10];
    const float* conv_b3 = (const float*)d_in[11];
    const float* cls_w1  = (const float*)d_in[12];
    const float* cls_b1  = (const float*)d_in[13];
    const float* cls_w2  = (const float*)d_in[14];
    const float* cls_b2  = (const float*)d_in[15];

    const int n = in_sizes[0] / FDIM;
    const int E = in_sizes[1] / 2;

    const int T = 256;
    const int gm = (n + 127) / 128;
    const int gN = (n + T - 1) / T;
    const int gE = (E + T - 1) / T;
    const int gAgg = (n * 32 + T - 1) / T;
    const long long eThreads = (long long)E * 32;
    const int gEdge = (int)((eThreads + T - 1) / T);

    // CSR build + normalization
    zero_int_kernel<<<gN, T>>>(n);
    count_kernel<<<gE, T>>>(ei, E);
    dis_kernel<<<gN, T>>>(n);
    scan_kernel<<<1, 1024>>>(n, E);
    fill_kernel<<<gE, T>>>(ei, E);

    // node encoder: buf1 = relu(nf@W1+b1e)@W2 + b2e
    sgemm_n128<false, true, true><<<gm, 256>>>(nf, 0, enc_w1, enc_b1, BUF0_OFF, n, FDIM);
    sgemm_n128<false, false, true><<<gm, 256>>>(nullptr, BUF0_OFF, enc_w2, enc_b2, BUF1_OFF, n, H);

    // conv1 (relu deferred to next GEMM input)
    sgemm_n128<false, false, false><<<gm, 256>>>(nullptr, BUF1_OFF, conv_w1, nullptr, BUF0_OFF, n, H);
    aggregate_kernel<<<gAgg, T>>>(BUF0_OFF, conv_b1, BUF2_OFF, n);

    // conv2
    sgemm_n128<true, false, false><<<gm, 256>>>(nullptr, BUF2_OFF, conv_w2, nullptr, BUF0_OFF, n, H);
    aggregate_kernel<<<gAgg, T>>>(BUF0_OFF, conv_b2, BUF1_OFF, n);

    // conv3 (no output relu anywhere downstream)
    sgemm_n128<true, false, false><<<gm, 256>>>(nullptr, BUF1_OFF, conv_w3, nullptr, BUF0_OFF, n, H);
    aggregate_kernel<<<gAgg, T>>>(BUF0_OFF, conv_b3, BUF2_OFF, n);

    // classifier partials: A = X@W1_top + cls_b1 (buf0), B = X@W1_bot (buf1)
    sgemm_n128<false, false, true><<<gm, 256>>>(nullptr, BUF2_OFF, cls_w1, cls_b1, BUF0_OFF, n, H);
    sgemm_n128<false, false, false><<<gm, 256>>>(nullptr, BUF2_OFF, cls_w1 + 128 * 128, nullptr, BUF1_OFF, n, H);

    // per-edge score
    edge_cls_kernel<<<gEdge, T>>>(ei, BUF0_OFF, BUF1_OFF, cls_w2, cls_b2, (float*)d_out, E);
}

// round 6
// speedup vs baseline: 2.2678x; 1.0446x over previous
#include <cuda_runtime.h>
#include <math.h>

#define FDIM 256
#define H 128
#define NMAX 50000
#define EMAX 1600000

// Scratch (allocation-free rule: __device__ globals)
#define BUF0_OFF 0
#define BUF1_OFF (NMAX * H)
#define BUF2_OFF (2 * NMAX * H)
__device__ float g_scratch[3 * NMAX * H];
__device__ float g_dis[NMAX];
__device__ int   g_cnt[NMAX];
__device__ int   g_fill[NMAX];
__device__ int   g_rowptr[NMAX + 1];
__device__ int   g_csr_src[EMAX];
__device__ float g_csr_norm[EMAX];
__device__ int   g_blocksum[64];
__device__ int   g_blockoff[64];

__device__ __forceinline__ const float* rsv(const float* p, int off) {
    return p ? p : (g_scratch + off);
}

// ---------------------------------------------------------------------------
// CSR build: count -> dis -> 3-phase scan -> fill
// ---------------------------------------------------------------------------
__global__ void zero_int_kernel(int n) {
    int i = blockIdx.x * blockDim.x + threadIdx.x;
    if (i < n) { g_cnt[i] = 0; g_fill[i] = 0; }
}

__global__ void count_kernel(const int* __restrict__ ei, int E) {
    int e = blockIdx.x * blockDim.x + threadIdx.x;
    if (e < E) atomicAdd(&g_cnt[ei[(size_t)E + e]], 1);
}

__global__ void dis_kernel(int n) {
    int i = blockIdx.x * blockDim.x + threadIdx.x;
    if (i < n) g_dis[i] = rsqrtf((float)(g_cnt[i] + 1));  // +1 self loop
}

// phase1: per-block (1024 elems) totals
__global__ void scan_phase1(int n) {
    int t = threadIdx.x;
    int base = blockIdx.x * 1024 + t * 4;
    int s = 0;
#pragma unroll
    for (int j = 0; j < 4; j++) { int i = base + j; if (i < n) s += g_cnt[i]; }
#pragma unroll
    for (int off = 16; off; off >>= 1) s += __shfl_xor_sync(0xffffffffu, s, off);
    __shared__ int wsum[8];
    if ((t & 31) == 0) wsum[t >> 5] = s;
    __syncthreads();
    if (t == 0) {
        int tot = 0;
#pragma unroll
        for (int w = 0; w < 8; w++) tot += wsum[w];
        g_blocksum[blockIdx.x] = tot;
    }
}

// phase2: exclusive scan of block totals (nb <= 64), 1 block of 64 threads
__global__ void scan_phase2(int nb) {
    __shared__ int sh[64];
    int t = threadIdx.x;
    int v = (t < nb) ? g_blocksum[t] : 0;
    sh[t] = v;
    __syncthreads();
    for (int off = 1; off < 64; off <<= 1) {
        int tmp = (t >= off) ? sh[t - off] : 0;
        __syncthreads();
        sh[t] += tmp;
        __syncthreads();
    }
    if (t < nb) g_blockoff[t] = sh[t] - v;  // exclusive
}

// phase3: per-block exclusive prefix + block offset -> rowptr
__global__ void scan_phase3(int n, int E) {
    int t = threadIdx.x;
    int base = blockIdx.x * 1024 + t * 4;
    int v[4]; int s = 0;
#pragma unroll
    for (int j = 0; j < 4; j++) { int i = base + j; v[j] = (i < n) ? g_cnt[i] : 0; s += v[j]; }
    int incl = s;
#pragma unroll
    for (int off = 1; off < 32; off <<= 1) {
        int tmp = __shfl_up_sync(0xffffffffu, incl, off);
        if ((t & 31) >= off) incl += tmp;
    }
    __shared__ int wtot[8];
    __shared__ int woff[8];
    if ((t & 31) == 31) wtot[t >> 5] = incl;
    __syncthreads();
    if (t < 8) {
        int wv = wtot[t];
        int wincl = wv;
#pragma unroll
        for (int off = 1; off < 8; off <<= 1) {
            int tmp = __shfl_up_sync(0x000000ffu, wincl, off);
            if (t >= off) wincl += tmp;
        }
        woff[t] = wincl - wv;
    }
    __syncthreads();
    int prefix = g_blockoff[blockIdx.x] + woff[t >> 5] + (incl - s);
#pragma unroll
    for (int j = 0; j < 4; j++) {
        int i = base + j;
        if (i < n) g_rowptr[i] = prefix;
        prefix += v[j];
    }
    if (blockIdx.x == 0 && t == 0) g_rowptr[n] = E;
}

__global__ void fill_kernel(const int* __restrict__ ei, int E) {
    int e = blockIdx.x * blockDim.x + threadIdx.x;
    if (e >= E) return;
    int s = ei[e];
    int d = ei[(size_t)E + e];
    int pos = g_rowptr[d] + atomicAdd(&g_fill[d], 1);
    g_csr_src[pos] = s;
    g_csr_norm[pos] = g_dis[s] * g_dis[d];
}

// ---------------------------------------------------------------------------
// SGEMM, N fixed to 128, double-buffered smem, BK=8, 256 thr, 8x8 per-thread
// ---------------------------------------------------------------------------
template <bool RIN, bool ROUT, bool BIAS>
__global__ __launch_bounds__(256)
void sgemm_n128(const float* __restrict__ Aext, int aOff,
                const float* __restrict__ W,
                const float* __restrict__ bias,
                int cOff, int M, int K) {
    const float* A = rsv(Aext, aOff);
    float* C = g_scratch + cOff;

    __shared__ float As[2][8][128];
    __shared__ float Bs[2][8][128];

    const int tid = threadIdx.x;
    const int rowBase = blockIdx.x * 128;

    const int innerRowA = tid >> 1;
    const int innerColA = (tid & 1) * 4;
    const int innerRowB = tid >> 5;
    const int innerColB = (tid & 31) * 4;

    const int tr = tid >> 4;
    const int tc = tid & 15;

    float acc[8][8];
#pragma unroll
    for (int i = 0; i < 8; i++)
#pragma unroll
        for (int j = 0; j < 8; j++) acc[i][j] = 0.0f;

    const int mA = rowBase + innerRowA;
    const bool validA = (mA < M);
    const float* Aptr = A + (size_t)mA * K;

    // prologue: load k-tile 0 into buffer 0
    {
        float4 av = make_float4(0.f, 0.f, 0.f, 0.f);
        if (validA) av = *(const float4*)(Aptr + innerColA);
        if (RIN) {
            av.x = fmaxf(av.x, 0.f); av.y = fmaxf(av.y, 0.f);
            av.z = fmaxf(av.z, 0.f); av.w = fmaxf(av.w, 0.f);
        }
        As[0][innerColA + 0][innerRowA] = av.x;
        As[0][innerColA + 1][innerRowA] = av.y;
        As[0][innerColA + 2][innerRowA] = av.z;
        As[0][innerColA + 3][innerRowA] = av.w;
        float4 bv = *(const float4*)(W + (size_t)innerRowB * 128 + innerColB);
        *(float4*)&Bs[0][innerRowB][innerColB] = bv;
    }
    __syncthreads();

    const int nIter = K >> 3;
    for (int it = 0; it < nIter; it++) {
        const int cur = it & 1;
        const bool has = (it + 1 < nIter);
        float4 avn = make_float4(0.f, 0.f, 0.f, 0.f);
        float4 bvn;
        if (has) {
            const int k0 = (it + 1) << 3;
            if (validA) avn = *(const float4*)(Aptr + k0 + innerColA);
            if (RIN) {
                avn.x = fmaxf(avn.x, 0.f); avn.y = fmaxf(avn.y, 0.f);
                avn.z = fmaxf(avn.z, 0.f); avn.w = fmaxf(avn.w, 0.f);
            }
            bvn = *(const float4*)(W + (size_t)(k0 + innerRowB) * 128 + innerColB);
        }

#pragma unroll
        for (int k = 0; k < 8; k++) {
            float rm[8], rn[8];
#pragma unroll
            for (int i = 0; i < 8; i++) rm[i] = As[cur][k][tr * 8 + i];
#pragma unroll
            for (int j = 0; j < 8; j++) rn[j] = Bs[cur][k][tc * 8 + j];
#pragma unroll
            for (int i = 0; i < 8; i++)
#pragma unroll
                for (int j = 0; j < 8; j++) acc[i][j] += rm[i] * rn[j];
        }

        if (has) {
            const int nxt = cur ^ 1;
            As[nxt][innerColA + 0][innerRowA] = avn.x;
            As[nxt][innerColA + 1][innerRowA] = avn.y;
            As[nxt][innerColA + 2][innerRowA] = avn.z;
            As[nxt][innerColA + 3][innerRowA] = avn.w;
            *(float4*)&Bs[nxt][innerRowB][innerColB] = bvn;
        }
        __syncthreads();
    }

#pragma unroll
    for (int i = 0; i < 8; i++) {
        int row = rowBase + tr * 8 + i;
        if (row >= M) continue;
#pragma unroll
        for (int j = 0; j < 8; j += 4) {
            int col = tc * 8 + j;
            float4 v;
            v.x = acc[i][j + 0];
            v.y = acc[i][j + 1];
            v.z = acc[i][j + 2];
            v.w = acc[i][j + 3];
            if (BIAS) {
                v.x += bias[col + 0]; v.y += bias[col + 1];
                v.z += bias[col + 2]; v.w += bias[col + 3];
            }
            if (ROUT) {
                v.x = fmaxf(v.x, 0.f); v.y = fmaxf(v.y, 0.f);
                v.z = fmaxf(v.z, 0.f); v.w = fmaxf(v.w, 0.f);
            }
            *(float4*)(C + (size_t)row * 128 + col) = v;
        }
    }
}

// ---------------------------------------------------------------------------
// GCN aggregation (gather, no atomics): one warp per dst node.
// ---------------------------------------------------------------------------
__global__ __launch_bounds__(256)
void aggregate_kernel(int xwOff, const float* __restrict__ bias,
                      int outOff, int n) {
    const float4* xw4 = (const float4*)(g_scratch + xwOff);
    float4* out4 = (float4*)(g_scratch + outOff);
    int d = (blockIdx.x * blockDim.x + threadIdx.x) >> 5;
    int lane = threadIdx.x & 31;
    if (d >= n) return;

    float di = g_dis[d];
    float sn = di * di;
    float4 b = ((const float4*)bias)[lane];
    float4 x = xw4[(size_t)d * 32 + lane];
    float4 acc;
    acc.x = b.x + sn * x.x; acc.y = b.y + sn * x.y;
    acc.z = b.z + sn * x.z; acc.w = b.w + sn * x.w;

    int i = g_rowptr[d];
    const int end = g_rowptr[d + 1];
    for (; i + 1 < end; i += 2) {
        int s0 = g_csr_src[i], s1 = g_csr_src[i + 1];
        float n0 = g_csr_norm[i], n1 = g_csr_norm[i + 1];
        float4 v0 = xw4[(size_t)s0 * 32 + lane];
        float4 v1 = xw4[(size_t)s1 * 32 + lane];
        acc.x += n0 * v0.x + n1 * v1.x;
        acc.y += n0 * v0.y + n1 * v1.y;
        acc.z += n0 * v0.z + n1 * v1.z;
        acc.w += n0 * v0.w + n1 * v1.w;
    }
    if (i < end) {
        int s0 = g_csr_src[i];
        float n0 = g_csr_norm[i];
        float4 v0 = xw4[(size_t)s0 * 32 + lane];
        acc.x += n0 * v0.x; acc.y += n0 * v0.y;
        acc.z += n0 * v0.z; acc.w += n0 * v0.w;
    }
    out4[(size_t)d * 32 + lane] = acc;
}

// ---------------------------------------------------------------------------
// Edge classifier: out[e] = sigmoid( dot(relu(A[src]+B[dst]), w2) + b2 )
// ---------------------------------------------------------------------------
__global__ void edge_cls_kernel(const int* __restrict__ ei,
                                int aOff, int bOff,
                                const float* __restrict__ w2,
                                const float* __restrict__ b2,
                                float* __restrict__ out, int E) {
    const float* Amat = g_scratch + aOff;
    const float* Bmat = g_scratch + bOff;
    int w = (blockIdx.x * blockDim.x + threadIdx.x) >> 5;
    int lane = threadIdx.x & 31;
    if (w >= E) return;
    int s = ei[w];
    int d = ei[(size_t)E + w];
    float4 a = ((const float4*)(Amat + (size_t)s * H))[lane];
    float4 b = ((const float4*)(Bmat + (size_t)d * H))[lane];
    float4 ww = ((const float4*)w2)[lane];
    float p = fmaxf(a.x + b.x, 0.f) * ww.x
            + fmaxf(a.y + b.y, 0.f) * ww.y
            + fmaxf(a.z + b.z, 0.f) * ww.z
            + fmaxf(a.w + b.w, 0.f) * ww.w;
#pragma unroll
    for (int off = 16; off; off >>= 1)
        p += __shfl_xor_sync(0xffffffffu, p, off);
    if (lane == 0) {
        float z = p + b2[0];
        out[w] = 1.0f / (1.0f + __expf(-z));
    }
}

// ---------------------------------------------------------------------------
extern "C" void kernel_launch(void* const* d_in, const int* in_sizes, int n_in,
                              void* d_out, int out_size) {
    const float* nf      = (const float*)d_in[0];
    const int*   ei      = (const int*)d_in[1];
    const float* enc_w1  = (const float*)d_in[2];
    const float* enc_b1  = (const float*)d_in[3];
    const float* enc_w2  = (const float*)d_in[4];
    const float* enc_b2  = (const float*)d_in[5];
    const float* conv_w1 = (const float*)d_in[6];
    const float* conv_b1 = (const float*)d_in[7];
    const float* conv_w2 = (const float*)d_in[8];
    const float* conv_b2 = (const float*)d_in[9];
    const float* conv_w3 = (const float*)d_in[10];
    const float* conv_b3 = (const float*)d_in[11];
    const float* cls_w1  = (const float*)d_in[12];
    const float* cls_b1  = (const float*)d_in[13];
    const float* cls_w2  = (const float*)d_in[14];
    const float* cls_b2  = (const float*)d_in[15];

    const int n = in_sizes[0] / FDIM;
    const int E = in_sizes[1] / 2;

    const int T = 256;
    const int gm = (n + 127) / 128;
    const int gN = (n + T - 1) / T;
    const int gE = (E + T - 1) / T;
    const int gAgg = (n * 32 + T - 1) / T;
    const int nb = (n + 1023) / 1024;
    const long long eThreads = (long long)E * 32;
    const int gEdge = (int)((eThreads + T - 1) / T);

    // CSR build + normalization
    zero_int_kernel<<<gN, T>>>(n);
    count_kernel<<<gE, T>>>(ei, E);
    dis_kernel<<<gN, T>>>(n);
    scan_phase1<<<nb, 256>>>(n);
    scan_phase2<<<1, 64>>>(nb);
    scan_phase3<<<nb, 256>>>(n, E);
    fill_kernel<<<gE, T>>>(ei, E);

    // node encoder: buf1 = relu(nf@W1+b1e)@W2 + b2e
    sgemm_n128<false, true, true><<<gm, 256>>>(nf, 0, enc_w1, enc_b1, BUF0_OFF, n, FDIM);
    sgemm_n128<false, false, true><<<gm, 256>>>(nullptr, BUF0_OFF, enc_w2, enc_b2, BUF1_OFF, n, H);

    // conv1 (relu deferred to next GEMM input)
    sgemm_n128<false, false, false><<<gm, 256>>>(nullptr, BUF1_OFF, conv_w1, nullptr, BUF0_OFF, n, H);
    aggregate_kernel<<<gAgg, T>>>(BUF0_OFF, conv_b1, BUF2_OFF, n);

    // conv2
    sgemm_n128<true, false, false><<<gm, 256>>>(nullptr, BUF2_OFF, conv_w2, nullptr, BUF0_OFF, n, H);
    aggregate_kernel<<<gAgg, T>>>(BUF0_OFF, conv_b2, BUF1_OFF, n);

    // conv3
    sgemm_n128<true, false, false><<<gm, 256>>>(nullptr, BUF1_OFF, conv_w3, nullptr, BUF0_OFF, n, H);
    aggregate_kernel<<<gAgg, T>>>(BUF0_OFF, conv_b3, BUF2_OFF, n);

    // classifier partials: A = X@W1_top + cls_b1 (buf0), B = X@W1_bot (buf1)
    sgemm_n128<false, false, true><<<gm, 256>>>(nullptr, BUF2_OFF, cls_w1, cls_b1, BUF0_OFF, n, H);
    sgemm_n128<false, false, false><<<gm, 256>>>(nullptr, BUF2_OFF, cls_w1 + 128 * 128, nullptr, BUF1_OFF, n, H);

    // per-edge score
    edge_cls_kernel<<<gEdge, T>>>(ei, BUF0_OFF, BUF1_OFF, cls_w2, cls_b2, (float*)d_out, E);
}